// round 1
// baseline (speedup 1.0000x reference)
#include <cuda_runtime.h>
#include <math.h>
#include <stdint.h>

#define HH 360
#define WW 640
#define NP (HH*WW)          // 230400
#define NPLANES 1000
#define NBLK 900            // NP / 256
#define CBLK 225            // NP / 1024
#define MINPTS 5000

#define CXc 334.081f
#define CYc 169.808f
#define FXc 460.585f
#define FYc 460.268f

// ---------------- scratch (static device globals; no allocation) ----------------
__device__ float4   g_plane[NPLANES];
__device__ int      g_counts[NPLANES];
__device__ float    g_partA[NBLK * 6];   // cnt, dx2, dy2, dz2, dlog2, max
__device__ float    g_partB[NBLK * 2];   // sum|zc-zmax|, sum|zc-zmin|
__device__ float    g_sc[8];             // 0:lossX 1:lossY 2:lossZ 3:RMSE_log 4:loss17 5:maxv 6:thresh
__device__ float    g_bp[8];             // a,b,c,d,tz,r20,r21,r22
__device__ unsigned g_zmax_key, g_zmin_key;
__device__ int      g_icnt;

// ---------------- helpers ----------------
__device__ __forceinline__ uint32_t rotl32(uint32_t v, int s) { return (v << s) | (v >> (32 - s)); }

// jax threefry2x32 (matches jax/_src/prng.py lowering)
__device__ __forceinline__ void threefry2x32(uint32_t k0, uint32_t k1, uint32_t x0, uint32_t x1,
                                             uint32_t& o0, uint32_t& o1) {
    uint32_t ks2 = k0 ^ k1 ^ 0x1BD11BDAu;
    x0 += k0; x1 += k1;
#define TFR(R) { x0 += x1; x1 = rotl32(x1, R); x1 ^= x0; }
    TFR(13) TFR(15) TFR(26) TFR(6)
    x0 += k1;  x1 += ks2 + 1u;
    TFR(17) TFR(29) TFR(16) TFR(24)
    x0 += ks2; x1 += k0 + 2u;
    TFR(13) TFR(15) TFR(26) TFR(6)
    x0 += k0;  x1 += k1 + 3u;
    TFR(17) TFR(29) TFR(16) TFR(24)
    x0 += k1;  x1 += ks2 + 4u;
    TFR(13) TFR(15) TFR(26) TFR(6)
    x0 += ks2; x1 += k0 + 5u;
#undef TFR
    o0 = x0; o1 = x1;
}

// monotone float <-> unsigned encoding for atomic min/max
__device__ __forceinline__ unsigned fenc(float f) {
    unsigned u = __float_as_uint(f);
    return (u & 0x80000000u) ? ~u : (u | 0x80000000u);
}
__device__ __forceinline__ float fdec(unsigned k) {
    return __uint_as_float((k & 0x80000000u) ? (k ^ 0x80000000u) : ~k);
}

// pts[i] : fake_pcd*1000, eps-substituted, NaN->0, / maxv
__device__ __forceinline__ void pts_at(const float* __restrict__ fake, int p, float maxv,
                                       float& x, float& y, float& z) {
    float d = fake[p];
    bool valid = (d > 0.0f) && (d < 65535.0f);
    int r = p / WW, c = p - r * WW;
    float zz = d / 1000.0f;
    float px = zz * ((float)c - CXc) / FXc * 1000.0f;
    float py = zz * ((float)r - CYc) / FYc * 1000.0f;
    float pz = zz * 1000.0f;
    if (px == 0.0f) px = 1e-7f;
    if (py == 0.0f) py = 1e-7f;
    if (pz == 0.0f) pz = 1e-7f;
    if (!valid) { px = 0.0f; py = 0.0f; pz = 0.0f; }
    x = px / maxv; y = py / maxv; z = pz / maxv;
}

// deterministic block reductions (blockDim = 256)
__device__ __forceinline__ float bredsum(float v) {
    __shared__ float sh[8];
    __syncthreads();
    int lane = threadIdx.x & 31, w = threadIdx.x >> 5;
    for (int o = 16; o; o >>= 1) v += __shfl_down_sync(0xffffffffu, v, o);
    if (lane == 0) sh[w] = v;
    __syncthreads();
    float r = 0.0f;
    if (threadIdx.x == 0) { for (int i = 0; i < 8; i++) r += sh[i]; }
    return r;
}
__device__ __forceinline__ float bredmax(float v) {
    __shared__ float sh[8];
    __syncthreads();
    int lane = threadIdx.x & 31, w = threadIdx.x >> 5;
    for (int o = 16; o; o >>= 1) v = fmaxf(v, __shfl_down_sync(0xffffffffu, v, o));
    if (lane == 0) sh[w] = v;
    __syncthreads();
    float r = -INFINITY;
    if (threadIdx.x == 0) { for (int i = 0; i < 8; i++) r = fmaxf(r, sh[i]); }
    return r;
}
__device__ __forceinline__ float bredmin(float v) {
    __shared__ float sh[8];
    __syncthreads();
    int lane = threadIdx.x & 31, w = threadIdx.x >> 5;
    for (int o = 16; o; o >>= 1) v = fminf(v, __shfl_down_sync(0xffffffffu, v, o));
    if (lane == 0) sh[w] = v;
    __syncthreads();
    float r = INFINITY;
    if (threadIdx.x == 0) { for (int i = 0; i < 8; i++) r = fminf(r, sh[i]); }
    return r;
}
__device__ __forceinline__ int bredsumi(int v) {
    __shared__ int sh[8];
    __syncthreads();
    int lane = threadIdx.x & 31, w = threadIdx.x >> 5;
    for (int o = 16; o; o >>= 1) v += __shfl_down_sync(0xffffffffu, v, o);
    if (lane == 0) sh[w] = v;
    __syncthreads();
    int r = 0;
    if (threadIdx.x == 0) { for (int i = 0; i < 8; i++) r += sh[i]; }
    return r;
}

// ---------------- K1: init ----------------
__global__ void k_init() {
    int t = blockIdx.x * blockDim.x + threadIdx.x;
    if (t < NPLANES) g_counts[t] = 0;
    if (t == 0) {
        g_icnt = 0;
        g_zmax_key = fenc(-INFINITY);
        g_zmin_key = fenc(INFINITY);
    }
}

// ---------------- K2: pixel pass ----------------
__global__ void k_pixel(const float* __restrict__ fake, const float* __restrict__ real) {
    int p = blockIdx.x * 256 + threadIdx.x;
    float rd = real[p], fd = fake[p];
    int r = p / WW, c = p - r * WW;
    float cc = (float)c, rr = (float)r;
    bool vr = (rd > 0.0f) && (rd < 65535.0f);
    bool vf = (fd > 0.0f) && (fd < 65535.0f);

    float rz = rd / 1000.0f;
    float rX = rz * (cc - CXc) / FXc * 1000.0f;
    float rY = rz * (rr - CYc) / FYc * 1000.0f;
    float rZ = rz * 1000.0f;
    if (rX == 0.0f) rX = 1e-7f;
    if (rY == 0.0f) rY = 1e-7f;
    if (rZ == 0.0f) rZ = 1e-7f;

    float fz = fd / 1000.0f;
    float fX = fz * (cc - CXc) / FXc * 1000.0f;
    float fY = fz * (rr - CYc) / FYc * 1000.0f;
    float fZ = fz * 1000.0f;
    if (fX == 0.0f) fX = 1e-7f;
    if (fY == 0.0f) fY = 1e-7f;
    if (fZ == 0.0f) fZ = 1e-7f;

    bool m = vr && vf;
    float dx = m ? (rX - fX) : 0.0f;
    float dy = m ? (rY - fY) : 0.0f;
    float dz = m ? (rZ - fZ) : 0.0f;
    float dl = m ? (logf(fabsf(rZ)) - logf(fabsf(fZ))) : 0.0f;

    float fx0 = vf ? fX : 0.0f, fy0 = vf ? fY : 0.0f, fz0 = vf ? fZ : 0.0f;
    float lm = fmaxf(fmaxf(fx0, fy0), fz0);

    float scnt = bredsum(m ? 1.0f : 0.0f);
    float sdx  = bredsum(dx * dx);
    float sdy  = bredsum(dy * dy);
    float sdz  = bredsum(dz * dz);
    float sdl  = bredsum(dl * dl);
    float smx  = bredmax(lm);
    if (threadIdx.x == 0) {
        float* pa = &g_partA[blockIdx.x * 6];
        pa[0] = scnt; pa[1] = sdx; pa[2] = sdy; pa[3] = sdz; pa[4] = sdl; pa[5] = smx;
    }
}

// ---------------- K3: scalar reduce ----------------
__global__ void k_scalars(const int* __restrict__ epoch_ptr) {
    int tid = threadIdx.x;
    float s0 = 0, s1 = 0, s2 = 0, s3 = 0, s4 = 0, mx = -INFINITY;
    for (int b = tid; b < NBLK; b += 256) {
        const float* pa = &g_partA[b * 6];
        s0 += pa[0]; s1 += pa[1]; s2 += pa[2]; s3 += pa[3]; s4 += pa[4];
        mx = fmaxf(mx, pa[5]);
    }
    s0 = bredsum(s0); s1 = bredsum(s1); s2 = bredsum(s2); s3 = bredsum(s3); s4 = bredsum(s4);
    mx = bredmax(mx);
    if (tid == 0) {
        float cnt = fmaxf(s0, 1.0f);
        float lossX = sqrtf(s1 / cnt);
        float lossY = sqrtf(s2 / cnt);
        float lossZ = sqrtf(s3 / cnt);
        float RMSE_log = 10000.0f * sqrtf(s4 / cnt);
        float loss17 = RMSE_log * fabsf(10.0f * (3.0f - expf(lossX) - expf(lossY) - expf(lossZ)));
        int ep = epoch_ptr[0];
        float th = fmaxf((float)(0.025 - 0.001 * (double)ep), 0.005f);
        g_sc[0] = lossX; g_sc[1] = lossY; g_sc[2] = lossZ;
        g_sc[3] = RMSE_log; g_sc[4] = loss17; g_sc[5] = mx; g_sc[6] = th;
    }
}

// ---------------- K4: plane setup (threefry sampling) ----------------
__global__ void k_planes(const float* __restrict__ fake) {
    int t = blockIdx.x * 256 + threadIdx.x;
    if (t >= NPLANES) return;
    // k2 = second key of fold-like split of key(42) = threefry((0,42),(0,1))
    uint32_t ka, kb;
    threefry2x32(0u, 42u, 0u, 1u, ka, kb);
    float maxv = g_sc[5];
    float P[3][3];
#pragma unroll
    for (int j = 0; j < 3; j++) {
        uint32_t o0, o1;
        threefry2x32(ka, kb, 0u, (uint32_t)(t * 3 + j), o0, o1);
        uint32_t idx = (o0 ^ o1) % (uint32_t)NP;   // randint multiplier wraps to 0 for span=230400
        pts_at(fake, (int)idx, maxv, P[j][0], P[j][1], P[j][2]);
    }
    float ax = P[1][0] - P[0][0], ay = P[1][1] - P[0][1], az = P[1][2] - P[0][2];
    float bx = P[2][0] - P[0][0], by = P[2][1] - P[0][1], bz = P[2][2] - P[0][2];
    float nx = ay * bz - az * by;
    float ny = az * bx - ax * bz;
    float nz = ax * by - ay * bx;
    float nn = sqrtf(nx * nx + ny * ny + nz * nz);
    nx /= nn; ny /= nn; nz /= nn;
    float kk = -(nx * P[1][0] + ny * P[1][1] + nz * P[1][2]);
    g_plane[t] = make_float4(nx, ny, nz, kk);
}

// ---------------- K5: fused dist + inlier count (the hot kernel) ----------------
__global__ void __launch_bounds__(256) k_count(const float* __restrict__ fake) {
    __shared__ float4 spl[NPLANES];      // 16000 B
    __shared__ int    scnt[8 * NPLANES]; // 32000 B
    int tid = threadIdx.x;
    for (int i = tid; i < NPLANES; i += 256) spl[i] = g_plane[i];
    for (int i = tid; i < 8 * NPLANES; i += 256) scnt[i] = 0;
    float maxv = g_sc[5];
    float th = g_sc[6];

    float px[4], py[4], pz[4];
#pragma unroll
    for (int k = 0; k < 4; k++) {
        int p = blockIdx.x * 1024 + k * 256 + tid;
        pts_at(fake, p, maxv, px[k], py[k], pz[k]);
    }
    __syncthreads();

    int lane = tid & 31;
    int* myrow = scnt + (tid >> 5) * NPLANES;
#pragma unroll 4
    for (int t = 0; t < NPLANES; t++) {
        float4 pl = spl[t];
        int c = 0;
#pragma unroll
        for (int k = 0; k < 4; k++) {
            float dd = fmaf(px[k], pl.x, fmaf(py[k], pl.y, fmaf(pz[k], pl.z, pl.w)));
            c += (fabsf(dd) <= th) ? 1 : 0;
        }
        unsigned cs = __reduce_add_sync(0xffffffffu, (unsigned)c);
        if (lane == 0) myrow[t] += (int)cs;
    }
    __syncthreads();
    for (int t = tid; t < NPLANES; t += 256) {
        int s = 0;
#pragma unroll
        for (int w = 0; w < 8; w++) s += scnt[w * NPLANES + t];
        atomicAdd(&g_counts[t], s);
    }
}

// ---------------- K6: argmax + best-plane geometry ----------------
__global__ void k_best() {
    __shared__ int ss[256], si[256];
    int tid = threadIdx.x;
    int bs = -2, bi = 0x7fffffff;
    for (int t = tid; t < NPLANES; t += 256) {
        int cnt = g_counts[t];
        int s = (cnt > MINPTS) ? cnt : -1;
        if (s > bs) { bs = s; bi = t; }   // ascending scan keeps first max per thread
    }
    ss[tid] = bs; si[tid] = bi;
    __syncthreads();
    for (int o = 128; o; o >>= 1) {
        if (tid < o) {
            if (ss[tid + o] > ss[tid] || (ss[tid + o] == ss[tid] && si[tid + o] < si[tid])) {
                ss[tid] = ss[tid + o]; si[tid] = si[tid + o];
            }
        }
        __syncthreads();
    }
    if (tid == 0) {
        int best = si[0];
        float4 pl = g_plane[best];
        float a = pl.x, b = pl.y, c = pl.z, d = pl.w;
        float tz = d / c;
        float n2 = a * a + b * b + c * c;
        float cos_t = c / sqrtf(n2);
        float sin_t = sqrtf((a * a + b * b) / n2);
        float sab = sqrtf(a * a + b * b);
        float u1 = b / sab;
        float u2 = -a / sab;
        g_bp[0] = a; g_bp[1] = b; g_bp[2] = c; g_bp[3] = d;
        g_bp[4] = tz;
        g_bp[5] = -u2 * sin_t;   // R[2][0]
        g_bp[6] =  u1 * sin_t;   // R[2][1]
        g_bp[7] =  cos_t;        // R[2][2]
    }
}

// ---------------- K7: zc pass 1 (icnt, zmin, zmax) ----------------
__global__ void k_zpass1(const float* __restrict__ fake) {
    int p = blockIdx.x * 256 + threadIdx.x;
    float maxv = g_sc[5], th = g_sc[6];
    float a = g_bp[0], b = g_bp[1], c = g_bp[2], d = g_bp[3];
    float tz = g_bp[4], r0 = g_bp[5], r1 = g_bp[6], r2 = g_bp[7];
    float x, y, z;
    pts_at(fake, p, maxv, x, y, z);
    float dist = x * a + y * b + z * c + d;
    bool inl = fabsf(dist) <= th;
    float zc = x * r0 + y * r1 + (z + tz) * r2;
    int ic = bredsumi(inl ? 1 : 0);
    float zmx = bredmax(inl ? zc : -INFINITY);
    float zmn = bredmin(inl ? zc : INFINITY);
    if (threadIdx.x == 0) {
        atomicAdd(&g_icnt, ic);
        atomicMax(&g_zmax_key, fenc(zmx));
        atomicMin(&g_zmin_key, fenc(zmn));
    }
}

// ---------------- K8: zc pass 2 (sums) ----------------
__global__ void k_zpass2(const float* __restrict__ fake) {
    int p = blockIdx.x * 256 + threadIdx.x;
    float maxv = g_sc[5], th = g_sc[6];
    float a = g_bp[0], b = g_bp[1], c = g_bp[2], d = g_bp[3];
    float tz = g_bp[4], r0 = g_bp[5], r1 = g_bp[6], r2 = g_bp[7];
    float zmax = fdec(g_zmax_key);
    float zmin = fdec(g_zmin_key);
    float x, y, z;
    pts_at(fake, p, maxv, x, y, z);
    float dist = x * a + y * b + z * c + d;
    bool inl = fabsf(dist) <= th;
    float zc = x * r0 + y * r1 + (z + tz) * r2;
    float sA = bredsum(inl ? fabsf(zc - zmax) : 0.0f);
    float sB = bredsum(inl ? fabsf(zc - zmin) : 0.0f);
    if (threadIdx.x == 0) {
        g_partB[blockIdx.x * 2 + 0] = sA;
        g_partB[blockIdx.x * 2 + 1] = sB;
    }
}

// ---------------- K9: finalize ----------------
__global__ void k_final(float* __restrict__ out) {
    int tid = threadIdx.x;
    float sA = 0, sB = 0;
    for (int b = tid; b < NBLK; b += 256) {
        sA += g_partB[b * 2 + 0];
        sB += g_partB[b * 2 + 1];
    }
    sA = bredsum(sA);
    sB = bredsum(sB);
    if (tid == 0) {
        float icnt = fmaxf((float)g_icnt, 1.0f);
        float below = sA / icnt;
        float above = sB / icnt;
        if (above == 0.0f) above = 1e-7f;
        float pmdg = 1000.0f * (above + below);
        float loss17 = g_sc[4];
        out[0] = g_sc[3];   // RMSE_log
        out[1] = g_sc[0];   // lossX
        out[2] = g_sc[1];   // lossY
        out[3] = g_sc[2];   // lossZ
        out[4] = pmdg;
        out[5] = loss17;
        out[6] = loss17 + pmdg;  // loss_curv
    }
}

// ---------------- launcher ----------------
extern "C" void kernel_launch(void* const* d_in, const int* in_sizes, int n_in,
                              void* d_out, int out_size) {
    const float* fake = (const float*)d_in[0];
    const float* real = (const float*)d_in[1];
    const int* epoch = (const int*)d_in[2];
    float* out = (float*)d_out;
    (void)in_sizes; (void)n_in; (void)out_size;

    k_init<<<4, 256>>>();
    k_pixel<<<NBLK, 256>>>(fake, real);
    k_scalars<<<1, 256>>>(epoch);
    k_planes<<<4, 256>>>(fake);
    k_count<<<CBLK, 256>>>(fake);
    k_best<<<1, 256>>>();
    k_zpass1<<<NBLK, 256>>>(fake);
    k_zpass2<<<NBLK, 256>>>(fake);
    k_final<<<1, 256>>>(out);
}

// round 2
// speedup vs baseline: 1.5848x; 1.5848x over previous
#include <cuda_runtime.h>
#include <math.h>
#include <stdint.h>

#define HH 360
#define WW 640
#define NP (HH*WW)          // 230400
#define NPLANES 1000
#define NPAIR   500
#define PXBLK 225           // blocks for 4px/thread kernels
#define MINPTS 5000

#define CXc 334.081f
#define CYc 169.808f
#define FXc 460.585f
#define FYc 460.268f

// k_count geometry: 46080 threads * 5px, 144 blocks * 320 threads
#define CB 144
#define CT 320
#define CW 10   // warps per count block

// ---------------- scratch ----------------
__device__ float4   g_plane[NPLANES];
__device__ int      g_counts[NPLANES];
__device__ float    g_partA[PXBLK * 6];
__device__ float    g_partB[PXBLK * 2];
__device__ float    g_sc[8];   // 0:lossX 1:lossY 2:lossZ 3:RMSE_log 4:loss17 5:maxv 6:thresh
__device__ float    g_bp[8];   // a,b,c,d,tz,r20,r21,r22
__device__ unsigned g_zmax_key, g_zmin_key;
__device__ int      g_icnt;

// ---------------- helpers ----------------
__host__ __device__ __forceinline__ uint32_t rotl32(uint32_t v, int s) { return (v << s) | (v >> (32 - s)); }

__host__ __device__ __forceinline__ void threefry2x32(uint32_t k0, uint32_t k1, uint32_t x0, uint32_t x1,
                                                      uint32_t& o0, uint32_t& o1) {
    uint32_t ks2 = k0 ^ k1 ^ 0x1BD11BDAu;
    x0 += k0; x1 += k1;
#define TFR(R) { x0 += x1; x1 = rotl32(x1, R); x1 ^= x0; }
    TFR(13) TFR(15) TFR(26) TFR(6)
    x0 += k1;  x1 += ks2 + 1u;
    TFR(17) TFR(29) TFR(16) TFR(24)
    x0 += ks2; x1 += k0 + 2u;
    TFR(13) TFR(15) TFR(26) TFR(6)
    x0 += k0;  x1 += k1 + 3u;
    TFR(17) TFR(29) TFR(16) TFR(24)
    x0 += k1;  x1 += ks2 + 4u;
    TFR(13) TFR(15) TFR(26) TFR(6)
    x0 += ks2; x1 += k0 + 5u;
#undef TFR
    o0 = x0; o1 = x1;
}

__device__ __forceinline__ unsigned fenc(float f) {
    unsigned u = __float_as_uint(f);
    return (u & 0x80000000u) ? ~u : (u | 0x80000000u);
}
__device__ __forceinline__ float fdec(unsigned k) {
    return __uint_as_float((k & 0x80000000u) ? (k ^ 0x80000000u) : ~k);
}

// packed f32x2 ops
__device__ __forceinline__ unsigned long long pk2(float lo, float hi) {
    unsigned long long r;
    asm("mov.b64 %0, {%1, %2};" : "=l"(r) : "f"(lo), "f"(hi));
    return r;
}
__device__ __forceinline__ void upk2(unsigned long long v, float& lo, float& hi) {
    asm("mov.b64 {%0, %1}, %2;" : "=f"(lo), "=f"(hi) : "l"(v));
}
__device__ __forceinline__ unsigned long long ffma2(unsigned long long a, unsigned long long b, unsigned long long c) {
    unsigned long long r;
    asm("fma.rn.f32x2 %0, %1, %2, %3;" : "=l"(r) : "l"(a), "l"(b), "l"(c));
    return r;
}

// pts (reference rounding) used for plane sampling
__device__ __forceinline__ void pts_at(const float* __restrict__ fake, int p, float maxv,
                                       float& x, float& y, float& z) {
    float d = fake[p];
    bool valid = (d > 0.0f) && (d < 65535.0f);
    int r = p / WW, c = p - r * WW;
    float zz = d / 1000.0f;
    float px = zz * ((float)c - CXc) / FXc * 1000.0f;
    float py = zz * ((float)r - CYc) / FYc * 1000.0f;
    float pz = zz * 1000.0f;
    if (px == 0.0f) px = 1e-7f;
    if (py == 0.0f) py = 1e-7f;
    if (pz == 0.0f) pz = 1e-7f;
    if (!valid) { px = 0.0f; py = 0.0f; pz = 0.0f; }
    x = px / maxv; y = py / maxv; z = pz / maxv;
}

// deterministic block reductions, blockDim = 256
__device__ __forceinline__ float bredsum(float v) {
    __shared__ float sh[8];
    __syncthreads();
    int lane = threadIdx.x & 31, w = threadIdx.x >> 5;
    for (int o = 16; o; o >>= 1) v += __shfl_down_sync(0xffffffffu, v, o);
    if (lane == 0) sh[w] = v;
    __syncthreads();
    float r = 0.0f;
    if (threadIdx.x == 0) { for (int i = 0; i < 8; i++) r += sh[i]; }
    return r;
}
__device__ __forceinline__ float bredmax(float v) {
    __shared__ float sh[8];
    __syncthreads();
    int lane = threadIdx.x & 31, w = threadIdx.x >> 5;
    for (int o = 16; o; o >>= 1) v = fmaxf(v, __shfl_down_sync(0xffffffffu, v, o));
    if (lane == 0) sh[w] = v;
    __syncthreads();
    float r = -INFINITY;
    if (threadIdx.x == 0) { for (int i = 0; i < 8; i++) r = fmaxf(r, sh[i]); }
    return r;
}
__device__ __forceinline__ float bredmin(float v) {
    __shared__ float sh[8];
    __syncthreads();
    int lane = threadIdx.x & 31, w = threadIdx.x >> 5;
    for (int o = 16; o; o >>= 1) v = fminf(v, __shfl_down_sync(0xffffffffu, v, o));
    if (lane == 0) sh[w] = v;
    __syncthreads();
    float r = INFINITY;
    if (threadIdx.x == 0) { for (int i = 0; i < 8; i++) r = fminf(r, sh[i]); }
    return r;
}
__device__ __forceinline__ int bredsumi(int v) {
    __shared__ int sh[8];
    __syncthreads();
    int lane = threadIdx.x & 31, w = threadIdx.x >> 5;
    for (int o = 16; o; o >>= 1) v += __shfl_down_sync(0xffffffffu, v, o);
    if (lane == 0) sh[w] = v;
    __syncthreads();
    int r = 0;
    if (threadIdx.x == 0) { for (int i = 0; i < 8; i++) r += sh[i]; }
    return r;
}
// blockDim = 1024 versions
__device__ __forceinline__ float bredsumL(float v) {
    __shared__ float sh[32];
    __syncthreads();
    int lane = threadIdx.x & 31, w = threadIdx.x >> 5;
    for (int o = 16; o; o >>= 1) v += __shfl_down_sync(0xffffffffu, v, o);
    if (lane == 0) sh[w] = v;
    __syncthreads();
    float r = 0.0f;
    if (threadIdx.x == 0) { for (int i = 0; i < 32; i++) r += sh[i]; }
    return r;
}
__device__ __forceinline__ float bredmaxL(float v) {
    __shared__ float sh[32];
    __syncthreads();
    int lane = threadIdx.x & 31, w = threadIdx.x >> 5;
    for (int o = 16; o; o >>= 1) v = fmaxf(v, __shfl_down_sync(0xffffffffu, v, o));
    if (lane == 0) sh[w] = v;
    __syncthreads();
    float r = -INFINITY;
    if (threadIdx.x == 0) { for (int i = 0; i < 32; i++) r = fmaxf(r, sh[i]); }
    return r;
}

// ---------------- K1: pixel pass (4 px/thread) + global init ----------------
__global__ void k_pixel(const float* __restrict__ fake, const float* __restrict__ real) {
    int tid = threadIdx.x;
    if (blockIdx.x == 0) {
        for (int i = tid; i < NPLANES; i += 256) g_counts[i] = 0;
        if (tid == 0) {
            g_icnt = 0;
            g_zmax_key = fenc(-INFINITY);
            g_zmin_key = fenc(INFINITY);
        }
    }
    int g = blockIdx.x * 256 + tid;
    float4 f4 = ((const float4*)fake)[g];
    float4 r4 = ((const float4*)real)[g];
    float acnt = 0, adx = 0, ady = 0, adz = 0, adl = 0, amx = -INFINITY;
#pragma unroll
    for (int j = 0; j < 4; j++) {
        int p = 4 * g + j;
        float fd = (&f4.x)[j], rd = (&r4.x)[j];
        int r = p / WW, c = p - r * WW;
        float cc = (float)c, rr = (float)r;
        bool vr = (rd > 0.0f) && (rd < 65535.0f);
        bool vf = (fd > 0.0f) && (fd < 65535.0f);

        float rz = rd / 1000.0f;
        float rX = rz * (cc - CXc) / FXc * 1000.0f;
        float rY = rz * (rr - CYc) / FYc * 1000.0f;
        float rZ = rz * 1000.0f;
        if (rX == 0.0f) rX = 1e-7f;
        if (rY == 0.0f) rY = 1e-7f;
        if (rZ == 0.0f) rZ = 1e-7f;

        float fz = fd / 1000.0f;
        float fX = fz * (cc - CXc) / FXc * 1000.0f;
        float fY = fz * (rr - CYc) / FYc * 1000.0f;
        float fZ = fz * 1000.0f;
        if (fX == 0.0f) fX = 1e-7f;
        if (fY == 0.0f) fY = 1e-7f;
        if (fZ == 0.0f) fZ = 1e-7f;

        bool m = vr && vf;
        if (m) {
            float dx = rX - fX, dy = rY - fY, dz = rZ - fZ;
            float dl = __logf(fabsf(rZ)) - __logf(fabsf(fZ));
            acnt += 1.0f;
            adx += dx * dx; ady += dy * dy; adz += dz * dz; adl += dl * dl;
        }
        if (vf) amx = fmaxf(amx, fmaxf(fmaxf(fX, fY), fZ));
    }
    float scnt = bredsum(acnt);
    float sdx  = bredsum(adx);
    float sdy  = bredsum(ady);
    float sdz  = bredsum(adz);
    float sdl  = bredsum(adl);
    float smx  = bredmax(amx);
    if (tid == 0) {
        float* pa = &g_partA[blockIdx.x * 6];
        pa[0] = scnt; pa[1] = sdx; pa[2] = sdy; pa[3] = sdz; pa[4] = sdl; pa[5] = smx;
    }
}

// ---------------- K2: scalars + plane sampling (1 block, 1024 threads) ----------------
__global__ void k_sp(const float* __restrict__ fake, const int* __restrict__ epoch_ptr,
                     uint32_t ka, uint32_t kb) {
    __shared__ float s_maxv;
    int tid = threadIdx.x;
    float s0 = 0, s1 = 0, s2 = 0, s3 = 0, s4 = 0, mx = -INFINITY;
    for (int b = tid; b < PXBLK; b += 1024) {
        const float* pa = &g_partA[b * 6];
        s0 += pa[0]; s1 += pa[1]; s2 += pa[2]; s3 += pa[3]; s4 += pa[4];
        mx = fmaxf(mx, pa[5]);
    }
    s0 = bredsumL(s0); s1 = bredsumL(s1); s2 = bredsumL(s2); s3 = bredsumL(s3); s4 = bredsumL(s4);
    mx = bredmaxL(mx);
    if (tid == 0) {
        float cnt = fmaxf(s0, 1.0f);
        float lossX = sqrtf(s1 / cnt);
        float lossY = sqrtf(s2 / cnt);
        float lossZ = sqrtf(s3 / cnt);
        float RMSE_log = 10000.0f * sqrtf(s4 / cnt);
        float loss17 = RMSE_log * fabsf(10.0f * (3.0f - expf(lossX) - expf(lossY) - expf(lossZ)));
        int ep = epoch_ptr[0];
        float th = fmaxf((float)(0.025 - 0.001 * (double)ep), 0.005f);
        g_sc[0] = lossX; g_sc[1] = lossY; g_sc[2] = lossZ;
        g_sc[3] = RMSE_log; g_sc[4] = loss17; g_sc[5] = mx; g_sc[6] = th;
        s_maxv = mx;
    }
    __syncthreads();
    if (tid < NPLANES) {
        float maxv = s_maxv;
        float P[3][3];
#pragma unroll
        for (int j = 0; j < 3; j++) {
            uint32_t o0, o1;
            threefry2x32(ka, kb, 0u, (uint32_t)(tid * 3 + j), o0, o1);
            uint32_t idx = (o0 ^ o1) % (uint32_t)NP;
            pts_at(fake, (int)idx, maxv, P[j][0], P[j][1], P[j][2]);
        }
        float ax = P[1][0] - P[0][0], ay = P[1][1] - P[0][1], az = P[1][2] - P[0][2];
        float bx = P[2][0] - P[0][0], by = P[2][1] - P[0][1], bz = P[2][2] - P[0][2];
        float nx = ay * bz - az * by;
        float ny = az * bx - ax * bz;
        float nz = ax * by - ay * bx;
        float nn = sqrtf(nx * nx + ny * ny + nz * nz);
        nx /= nn; ny /= nn; nz /= nn;
        float kk = -(nx * P[1][0] + ny * P[1][1] + nz * P[1][2]);
        g_plane[tid] = make_float4(nx, ny, nz, kk);
    }
}

// ---------------- K3: fused dist + inlier count ----------------
__global__ void __launch_bounds__(CT) k_count(const float* __restrict__ fake) {
    __shared__ float sA[NPLANES], sB[NPLANES], sC[NPLANES], sW[NPLANES]; // 16 KB
    __shared__ unsigned swarp[CW * NPAIR];                               // 20 KB
    int tid = threadIdx.x;
    for (int t = tid; t < NPLANES; t += CT) {
        float4 q = g_plane[t];
        sA[t] = q.x; sB[t] = q.y; sC[t] = q.z; sW[t] = q.w;
    }
    float maxv = g_sc[5];
    float th = g_sc[6];

    int g = blockIdx.x * CT + tid;      // 0..46079
    int p0 = g * 5;
    int row = p0 / WW;
    int col0 = p0 - row * WW;
    float v = ((float)row - CYc) / FYc;
    unsigned long long V = pk2(v, v);

    unsigned long long Up[5], Zp[5];
#pragma unroll
    for (int i = 0; i < 5; i++) {
        float d = __ldg(&fake[p0 + i]);
        bool val = (d > 0.0f) && (d < 65535.0f);
        float z = d / 1000.0f;
        float pz = z * 1000.0f;
        float Zi = val ? pz / maxv : 0.0f;
        float ui = ((float)(col0 + i) - CXc) / FXc;
        Up[i] = pk2(ui, ui);
        Zp[i] = pk2(Zi, Zi);
    }
    __syncthreads();

    int lane = tid & 31, wid = tid >> 5;
    const float2* pA = (const float2*)sA;
    const float2* pB = (const float2*)sB;
    const float2* pC = (const float2*)sC;
    const float2* pW = (const float2*)sW;
    unsigned* myrow = swarp + wid * NPAIR;

#pragma unroll 2
    for (int pr = 0; pr < NPAIR; pr++) {
        float2 a2 = pA[pr], b2 = pB[pr], c2 = pC[pr], w2 = pW[pr];
        unsigned long long A = pk2(a2.x, a2.y);
        unsigned long long Wp = pk2(w2.x, w2.y);
        unsigned long long K = ffma2(V, pk2(b2.x, b2.y), pk2(c2.x, c2.y));
        unsigned cpk = 0;
#pragma unroll
        for (int i = 0; i < 5; i++) {
            unsigned long long e = ffma2(Up[i], A, K);
            unsigned long long dd = ffma2(Zp[i], e, Wp);
            float lo, hi;
            upk2(dd, lo, hi);
            if (fabsf(lo) <= th) cpk += 1u;
            if (fabsf(hi) <= th) cpk += 65536u;
        }
        unsigned cs = __reduce_add_sync(0xffffffffu, cpk);
        if (lane == 0) myrow[pr] = cs;
    }
    __syncthreads();
    for (int pr = tid; pr < NPAIR; pr += CT) {
        unsigned s = 0;
#pragma unroll
        for (int w = 0; w < CW; w++) s += swarp[w * NPAIR + pr];
        atomicAdd(&g_counts[2 * pr],     (int)(s & 0xffffu));
        atomicAdd(&g_counts[2 * pr + 1], (int)(s >> 16));
    }
}

// ---------------- K4: zpass1 (argmax + geometry + icnt/zmin/zmax) ----------------
__global__ void k_zpass1(const float* __restrict__ fake) {
    __shared__ int ss[256], si[256];
    __shared__ float sbp[8];
    int tid = threadIdx.x;
    int bs = -2, bi = 0x7fffffff;
    for (int t = tid; t < NPLANES; t += 256) {
        int cnt = g_counts[t];
        int s = (cnt > MINPTS) ? cnt : -1;
        if (s > bs) { bs = s; bi = t; }
    }
    ss[tid] = bs; si[tid] = bi;
    __syncthreads();
    for (int o = 128; o; o >>= 1) {
        if (tid < o) {
            if (ss[tid + o] > ss[tid] || (ss[tid + o] == ss[tid] && si[tid + o] < si[tid])) {
                ss[tid] = ss[tid + o]; si[tid] = si[tid + o];
            }
        }
        __syncthreads();
    }
    if (tid == 0) {
        int best = si[0];
        float4 pl = g_plane[best];
        float a = pl.x, b = pl.y, c = pl.z, d = pl.w;
        float tz = d / c;
        float n2 = a * a + b * b + c * c;
        float cos_t = c / sqrtf(n2);
        float sin_t = sqrtf((a * a + b * b) / n2);
        float sab = sqrtf(a * a + b * b);
        float u1 = b / sab;
        float u2 = -a / sab;
        sbp[0] = a; sbp[1] = b; sbp[2] = c; sbp[3] = d;
        sbp[4] = tz;
        sbp[5] = -u2 * sin_t;
        sbp[6] =  u1 * sin_t;
        sbp[7] =  cos_t;
        if (blockIdx.x == 0) {
            g_bp[0] = a; g_bp[1] = b; g_bp[2] = c; g_bp[3] = d;
            g_bp[4] = tz; g_bp[5] = sbp[5]; g_bp[6] = sbp[6]; g_bp[7] = sbp[7];
        }
    }
    __syncthreads();
    float a = sbp[0], b = sbp[1], c = sbp[2], w = sbp[3];
    float tz = sbp[4], r0 = sbp[5], r1 = sbp[6], r2 = sbp[7];
    float maxv = g_sc[5], th = g_sc[6];

    int g = blockIdx.x * 256 + tid;
    float4 f4 = ((const float4*)fake)[g];
    int ic = 0;
    float zmx = -INFINITY, zmn = INFINITY;
#pragma unroll
    for (int j = 0; j < 4; j++) {
        int p = 4 * g + j;
        float d = (&f4.x)[j];
        int r = p / WW, cl = p - r * WW;
        bool val = (d > 0.0f) && (d < 65535.0f);
        float z = d / 1000.0f;
        float pz = z * 1000.0f;
        float Z = val ? pz / maxv : 0.0f;
        float u = ((float)cl - CXc) / FXc;
        float v = ((float)r - CYc) / FYc;
        float K = fmaf(v, b, c);
        float e = fmaf(u, a, K);
        float dist = fmaf(Z, e, w);
        bool inl = fabsf(dist) <= th;
        float x = Z * u, y = Z * v;
        float zc = fmaf(x, r0, fmaf(y, r1, (Z + tz) * r2));
        if (inl) {
            ic += 1;
            zmx = fmaxf(zmx, zc);
            zmn = fminf(zmn, zc);
        }
    }
    int sic = bredsumi(ic);
    float szx = bredmax(zmx);
    float szn = bredmin(zmn);
    if (tid == 0) {
        atomicAdd(&g_icnt, sic);
        atomicMax(&g_zmax_key, fenc(szx));
        atomicMin(&g_zmin_key, fenc(szn));
    }
}

// ---------------- K5: zpass2 (sums) ----------------
__global__ void k_zpass2(const float* __restrict__ fake) {
    int tid = threadIdx.x;
    float a = g_bp[0], b = g_bp[1], c = g_bp[2], w = g_bp[3];
    float tz = g_bp[4], r0 = g_bp[5], r1 = g_bp[6], r2 = g_bp[7];
    float maxv = g_sc[5], th = g_sc[6];
    float zmax = fdec(g_zmax_key);
    float zmin = fdec(g_zmin_key);

    int g = blockIdx.x * 256 + tid;
    float4 f4 = ((const float4*)fake)[g];
    float aA = 0.0f, aB = 0.0f;
#pragma unroll
    for (int j = 0; j < 4; j++) {
        int p = 4 * g + j;
        float d = (&f4.x)[j];
        int r = p / WW, cl = p - r * WW;
        bool val = (d > 0.0f) && (d < 65535.0f);
        float z = d / 1000.0f;
        float pz = z * 1000.0f;
        float Z = val ? pz / maxv : 0.0f;
        float u = ((float)cl - CXc) / FXc;
        float v = ((float)r - CYc) / FYc;
        float K = fmaf(v, b, c);
        float e = fmaf(u, a, K);
        float dist = fmaf(Z, e, w);
        bool inl = fabsf(dist) <= th;
        float x = Z * u, y = Z * v;
        float zc = fmaf(x, r0, fmaf(y, r1, (Z + tz) * r2));
        if (inl) {
            aA += fabsf(zc - zmax);
            aB += fabsf(zc - zmin);
        }
    }
    float sA = bredsum(aA);
    float sB = bredsum(aB);
    if (tid == 0) {
        g_partB[blockIdx.x * 2 + 0] = sA;
        g_partB[blockIdx.x * 2 + 1] = sB;
    }
}

// ---------------- K6: finalize ----------------
__global__ void k_final(float* __restrict__ out) {
    int tid = threadIdx.x;
    float sA = 0, sB = 0;
    for (int b = tid; b < PXBLK; b += 256) {
        sA += g_partB[b * 2 + 0];
        sB += g_partB[b * 2 + 1];
    }
    sA = bredsum(sA);
    sB = bredsum(sB);
    if (tid == 0) {
        float icnt = fmaxf((float)g_icnt, 1.0f);
        float below = sA / icnt;
        float above = sB / icnt;
        if (above == 0.0f) above = 1e-7f;
        float pmdg = 1000.0f * (above + below);
        float loss17 = g_sc[4];
        out[0] = g_sc[3];
        out[1] = g_sc[0];
        out[2] = g_sc[1];
        out[3] = g_sc[2];
        out[4] = pmdg;
        out[5] = loss17;
        out[6] = loss17 + pmdg;
    }
}

// ---------------- launcher ----------------
extern "C" void kernel_launch(void* const* d_in, const int* in_sizes, int n_in,
                              void* d_out, int out_size) {
    const float* fake = (const float*)d_in[0];
    const float* real = (const float*)d_in[1];
    const int* epoch = (const int*)d_in[2];
    float* out = (float*)d_out;
    (void)in_sizes; (void)n_in; (void)out_size;

    // derived threefry key for jax.random.randint(key(42), ...) on host
    uint32_t ka, kb;
    threefry2x32(0u, 42u, 0u, 1u, ka, kb);

    k_pixel<<<PXBLK, 256>>>(fake, real);
    k_sp<<<1, 1024>>>(fake, epoch, ka, kb);
    k_count<<<CB, CT>>>(fake);
    k_zpass1<<<PXBLK, 256>>>(fake);
    k_zpass2<<<PXBLK, 256>>>(fake);
    k_final<<<1, 256>>>(out);
}